// round 1
// baseline (speedup 1.0000x reference)
#include <cuda_runtime.h>
#include <cuda_bf16.h>

// Problem constants
#define N_BOX  16384
#define KCTX   32
#define IN_F   608
#define HID    384
#define ALPHA  0.2f
#define NEG_INF -9e15f

// ---------------- scratch (device globals; no runtime allocation) ----------
__device__ float  g_Whall[(size_t)N_BOX * HID];   // 24 MB: h_i @ W_j
__device__ float2 g_st[N_BOX];                    // (si + a_b, t) per row
__device__ float  g_v[IN_F];                      // W_i @ a_i
__device__ float  g_u[IN_F];                      // W_j @ a_j
__device__ int    g_is64;                         // idx dtype flag

// ---------------- 0: detect index dtype (int64 vs int32) -------------------
__global__ void detect_kernel(const int* __restrict__ w) {
    __shared__ int ok;
    if (threadIdx.x == 0) ok = 1;
    __syncthreads();
    // If data is int64 little-endian with values in [-1, N): every odd word
    // is 0 (value>=0) or -1 (value==-1). For int32 data this pattern over
    // 1024 pairs is astronomically unlikely.
    for (int p = threadIdx.x; p < 1024; p += blockDim.x) {
        int lo = w[2 * p], hi = w[2 * p + 1];
        bool consistent = (hi == 0 && lo >= 0) || (hi == -1 && lo < 0);
        if (!consistent) ok = 0;
    }
    __syncthreads();
    if (threadIdx.x == 0) g_is64 = ok;
}

// ---------------- 1: v = W_i@a_i, u = W_j@a_j ------------------------------
__global__ __launch_bounds__(128) void vu_kernel(
    const float* __restrict__ Wi, const float* __restrict__ Wj,
    const float* __restrict__ ai, const float* __restrict__ aj) {
    int j = blockIdx.x;           // 0..IN_F-1
    int tid = threadIdx.x;        // 128
    float s1 = 0.f, s2 = 0.f;
    for (int h = tid; h < HID; h += 128) {
        s1 += Wi[j * HID + h] * ai[h];
        s2 += Wj[j * HID + h] * aj[h];
    }
    __shared__ float r1[4], r2[4];
    for (int o = 16; o > 0; o >>= 1) {
        s1 += __shfl_xor_sync(0xffffffffu, s1, o);
        s2 += __shfl_xor_sync(0xffffffffu, s2, o);
    }
    int lane = tid & 31, wid = tid >> 5;
    if (lane == 0) { r1[wid] = s1; r2[wid] = s2; }
    __syncthreads();
    if (tid == 0) {
        g_v[j] = r1[0] + r1[1] + r1[2] + r1[3];
        g_u[j] = r2[0] + r2[1] + r2[2] + r2[3];
    }
}

// ---------------- 2: st[n] = (h_i[n].v + a_b, h_i[n].u) --------------------
__global__ __launch_bounds__(256) void st_kernel(
    const float* __restrict__ h, const float* __restrict__ ab) {
    int warp = (blockIdx.x * 256 + threadIdx.x) >> 5;
    int lane = threadIdx.x & 31;
    if (warp >= N_BOX) return;
    const float* row = h + warp * IN_F;
    float sv = 0.f, su = 0.f;
#pragma unroll
    for (int i = 0; i < IN_F / 32; i++) {   // 608 = 19*32
        float x = row[lane + i * 32];
        sv += x * g_v[lane + i * 32];
        su += x * g_u[lane + i * 32];
    }
    for (int o = 16; o > 0; o >>= 1) {
        sv += __shfl_xor_sync(0xffffffffu, sv, o);
        su += __shfl_xor_sync(0xffffffffu, su, o);
    }
    if (lane == 0) g_st[warp] = make_float2(sv + ab[0], su);
}

// ---------------- 3: Wh_all = h_i @ W_j  (128x128x8 SIMT sgemm) -------------
#define BM 128
#define BN 128
#define BK 8
#define TM 8
#define TN 8

__global__ __launch_bounds__(256) void sgemm_kernel(
    const float* __restrict__ A,   // [M, K]  h_i
    const float* __restrict__ B,   // [K, Nc] W_j
    float* __restrict__ C) {       // [M, Nc]
    const int M = N_BOX, Nc = HID, K = IN_F;
    __shared__ float As[BK][BM];
    __shared__ float Bs[BK][BN];
    int tid = threadIdx.x;
    int cRow = blockIdx.y, cCol = blockIdx.x;
    A += cRow * BM * K;
    B += cCol * BN;
    C += cRow * BM * Nc + cCol * BN;

    int innerRowA = tid >> 1, innerColA = (tid & 1) * 4;   // 128 x 8 A tile
    int innerRowB = tid >> 5, innerColB = (tid & 31) * 4;  // 8 x 128 B tile
    int threadRow = tid >> 4, threadCol = tid & 15;

    float acc[TM][TN] = {};
    float regM[TM], regN[TN];

    for (int kk = 0; kk < K; kk += BK) {
        float4 a4 = *(const float4*)(A + innerRowA * K + kk + innerColA);
        As[innerColA + 0][innerRowA] = a4.x;
        As[innerColA + 1][innerRowA] = a4.y;
        As[innerColA + 2][innerRowA] = a4.z;
        As[innerColA + 3][innerRowA] = a4.w;
        *(float4*)&Bs[innerRowB][innerColB] =
            *(const float4*)(B + (kk + innerRowB) * Nc + innerColB);
        __syncthreads();
#pragma unroll
        for (int k = 0; k < BK; k++) {
            *(float4*)&regM[0] = *(const float4*)&As[k][threadRow * TM];
            *(float4*)&regM[4] = *(const float4*)&As[k][threadRow * TM + 4];
            *(float4*)&regN[0] = *(const float4*)&Bs[k][threadCol * TN];
            *(float4*)&regN[4] = *(const float4*)&Bs[k][threadCol * TN + 4];
#pragma unroll
            for (int i = 0; i < TM; i++)
#pragma unroll
                for (int j = 0; j < TN; j++)
                    acc[i][j] += regM[i] * regN[j];
        }
        __syncthreads();
    }
#pragma unroll
    for (int i = 0; i < TM; i++)
#pragma unroll
        for (int j = 0; j < TN; j += 4) {
            float4 o = make_float4(acc[i][j], acc[i][j + 1], acc[i][j + 2], acc[i][j + 3]);
            *(float4*)(C + (threadRow * TM + i) * Nc + threadCol * TN + j) = o;
        }
}

// ---------------- 4: per-row attention + aggregation ------------------------
__global__ __launch_bounds__(128) void attn_kernel(
    const void* __restrict__ idxp, float* __restrict__ out) {
    int n = blockIdx.x;
    int tid = threadIdx.x;
    __shared__ float s_att[KCTX];
    __shared__ int   s_idx[KCTX];

    if (tid < KCTX) {
        long long id;
        if (g_is64) id = ((const long long*)idxp)[(long long)n * KCTX + tid];
        else        id = ((const int*)idxp)[n * KCTX + tid];
        int  ii    = (int)id;
        bool valid = (id >= 0);
        float score;
        if (valid) {
            float sc = g_st[n].x + g_st[ii].y;          // si + a_b + t[idx]
            score = sc > 0.f ? sc : ALPHA * sc;         // LeakyReLU
        } else {
            score = NEG_INF;
        }
        // warp softmax over the 32 context slots
        float m = score;
        for (int o = 16; o > 0; o >>= 1)
            m = fmaxf(m, __shfl_xor_sync(0xffffffffu, m, o));
        float e = valid ? __expf(score - m) : 0.f;
        float s = e;
        for (int o = 16; o > 0; o >>= 1)
            s += __shfl_xor_sync(0xffffffffu, s, o);
        s_att[tid] = (s > 0.f) ? (e / s) : 0.f;
        s_idx[tid] = ii;
    }
    __syncthreads();

    float acc0 = 0.f, acc1 = 0.f, acc2 = 0.f;
#pragma unroll
    for (int k = 0; k < KCTX; k++) {
        float a = s_att[k];
        if (a != 0.f) {                  // uniform across block; skips padding
            const float* row = g_Whall + s_idx[k] * HID;
            acc0 += a * row[tid];
            acc1 += a * row[tid + 128];
            acc2 += a * row[tid + 256];
        }
    }
    int o = n * HID;
    out[o + tid]       = acc0;
    out[o + tid + 128] = acc1;
    out[o + tid + 256] = acc2;
}

// ---------------- launch -----------------------------------------------------
extern "C" void kernel_launch(void* const* d_in, const int* in_sizes, int n_in,
                              void* d_out, int out_size) {
    const float* h_i = (const float*)d_in[0];
    const void*  idx = d_in[1];
    const float* W_i = (const float*)d_in[2];
    const float* W_j = (const float*)d_in[3];
    const float* a_i = (const float*)d_in[4];
    const float* a_j = (const float*)d_in[5];
    const float* a_b = (const float*)d_in[6];
    float* out = (float*)d_out;

    detect_kernel<<<1, 256>>>((const int*)idx);
    vu_kernel<<<IN_F, 128>>>(W_i, W_j, a_i, a_j);

    float* whall_ptr = nullptr;  // kernels reference g_Whall directly
    (void)whall_ptr;
    dim3 gemm_grid(HID / BN, N_BOX / BM);
    {
        // C = g_Whall — pass via device symbol: use a small shim kernel? No:
        // sgemm writes through its C argument; get address at launch via
        // a __device__ global is not host-visible without cudaGetSymbolAddress
        // (which is allowed — it's not an allocation). Done below.
    }
    void* whall_dev = nullptr;
    cudaGetSymbolAddress(&whall_dev, g_Whall);
    sgemm_kernel<<<gemm_grid, 256>>>(h_i, W_j, (float*)whall_dev);

    st_kernel<<<(N_BOX * 32 + 255) / 256, 256>>>(h_i, a_b);
    attn_kernel<<<N_BOX, 128>>>(idx, out);
}

// round 2
// speedup vs baseline: 1.0079x; 1.0079x over previous
#include <cuda_runtime.h>
#include <cuda_bf16.h>

// Problem constants
#define N_BOX  16384
#define KCTX   32
#define IN_F   608
#define HID    384
#define ALPHA  0.2f
#define NEG_INF -9e15f

// ---------------- scratch (device globals; no runtime allocation) ----------
__device__ float  g_Whall[(size_t)N_BOX * HID];   // 24 MB: h_i @ W_j
__device__ float2 g_st[N_BOX];                    // (si + a_b, t) per row
__device__ float  g_v[IN_F];                      // W_i @ a_i
__device__ float  g_u[IN_F];                      // W_j @ a_j
__device__ int    g_is64;                         // idx dtype flag

// ---------------- 0: detect index dtype (int64 vs int32) -------------------
__global__ void detect_kernel(const int* __restrict__ w) {
    __shared__ int ok;
    if (threadIdx.x == 0) ok = 1;
    __syncthreads();
    // If data is int64 little-endian with values in [-1, N): every odd word
    // is 0 (value>=0) or -1 (value==-1). For int32 data this pattern over
    // 1024 pairs is astronomically unlikely.
    for (int p = threadIdx.x; p < 1024; p += blockDim.x) {
        int lo = w[2 * p], hi = w[2 * p + 1];
        bool consistent = (hi == 0 && lo >= 0) || (hi == -1 && lo < 0);
        if (!consistent) ok = 0;
    }
    __syncthreads();
    if (threadIdx.x == 0) g_is64 = ok;
}

// ---------------- 1: v = W_i@a_i, u = W_j@a_j ------------------------------
__global__ __launch_bounds__(128) void vu_kernel(
    const float* __restrict__ Wi, const float* __restrict__ Wj,
    const float* __restrict__ ai, const float* __restrict__ aj) {
    int j = blockIdx.x;           // 0..IN_F-1
    int tid = threadIdx.x;        // 128
    float s1 = 0.f, s2 = 0.f;
    for (int h = tid; h < HID; h += 128) {
        s1 += Wi[j * HID + h] * ai[h];
        s2 += Wj[j * HID + h] * aj[h];
    }
    __shared__ float r1[4], r2[4];
    for (int o = 16; o > 0; o >>= 1) {
        s1 += __shfl_xor_sync(0xffffffffu, s1, o);
        s2 += __shfl_xor_sync(0xffffffffu, s2, o);
    }
    int lane = tid & 31, wid = tid >> 5;
    if (lane == 0) { r1[wid] = s1; r2[wid] = s2; }
    __syncthreads();
    if (tid == 0) {
        g_v[j] = r1[0] + r1[1] + r1[2] + r1[3];
        g_u[j] = r2[0] + r2[1] + r2[2] + r2[3];
    }
}

// ---------------- 2: st[n] = (h_i[n].v + a_b, h_i[n].u) --------------------
__global__ __launch_bounds__(256) void st_kernel(
    const float* __restrict__ h, const float* __restrict__ ab) {
    int warp = (blockIdx.x * 256 + threadIdx.x) >> 5;
    int lane = threadIdx.x & 31;
    if (warp >= N_BOX) return;
    const float* row = h + warp * IN_F;
    float sv = 0.f, su = 0.f;
#pragma unroll
    for (int i = 0; i < IN_F / 32; i++) {   // 608 = 19*32
        float x = row[lane + i * 32];
        sv += x * g_v[lane + i * 32];
        su += x * g_u[lane + i * 32];
    }
    for (int o = 16; o > 0; o >>= 1) {
        sv += __shfl_xor_sync(0xffffffffu, sv, o);
        su += __shfl_xor_sync(0xffffffffu, su, o);
    }
    if (lane == 0) g_st[warp] = make_float2(sv + ab[0], su);
}

// ---------------- 3: Wh_all = h_i @ W_j  (128x128x8 SIMT sgemm) -------------
#define BM 128
#define BN 128
#define BK 8
#define TM 8
#define TN 8

__global__ __launch_bounds__(256) void sgemm_kernel(
    const float* __restrict__ A,   // [M, K]  h_i
    const float* __restrict__ B,   // [K, Nc] W_j
    float* __restrict__ C) {       // [M, Nc]
    const int M = N_BOX, Nc = HID, K = IN_F;
    __shared__ float As[BK][BM];
    __shared__ float Bs[BK][BN];
    int tid = threadIdx.x;
    int cRow = blockIdx.y, cCol = blockIdx.x;
    A += cRow * BM * K;
    B += cCol * BN;
    C += cRow * BM * Nc + cCol * BN;

    int innerRowA = tid >> 1, innerColA = (tid & 1) * 4;   // 128 x 8 A tile
    int innerRowB = tid >> 5, innerColB = (tid & 31) * 4;  // 8 x 128 B tile
    int threadRow = tid >> 4, threadCol = tid & 15;

    float acc[TM][TN] = {};
    float regM[TM], regN[TN];

    for (int kk = 0; kk < K; kk += BK) {
        float4 a4 = *(const float4*)(A + innerRowA * K + kk + innerColA);
        As[innerColA + 0][innerRowA] = a4.x;
        As[innerColA + 1][innerRowA] = a4.y;
        As[innerColA + 2][innerRowA] = a4.z;
        As[innerColA + 3][innerRowA] = a4.w;
        *(float4*)&Bs[innerRowB][innerColB] =
            *(const float4*)(B + (kk + innerRowB) * Nc + innerColB);
        __syncthreads();
#pragma unroll
        for (int k = 0; k < BK; k++) {
            *(float4*)&regM[0] = *(const float4*)&As[k][threadRow * TM];
            *(float4*)&regM[4] = *(const float4*)&As[k][threadRow * TM + 4];
            *(float4*)&regN[0] = *(const float4*)&Bs[k][threadCol * TN];
            *(float4*)&regN[4] = *(const float4*)&Bs[k][threadCol * TN + 4];
#pragma unroll
            for (int i = 0; i < TM; i++)
#pragma unroll
                for (int j = 0; j < TN; j++)
                    acc[i][j] += regM[i] * regN[j];
        }
        __syncthreads();
    }
#pragma unroll
    for (int i = 0; i < TM; i++)
#pragma unroll
        for (int j = 0; j < TN; j += 4) {
            float4 o = make_float4(acc[i][j], acc[i][j + 1], acc[i][j + 2], acc[i][j + 3]);
            *(float4*)(C + (threadRow * TM + i) * Nc + threadCol * TN + j) = o;
        }
}

// ---------------- 4: per-row attention + aggregation ------------------------
__global__ __launch_bounds__(128) void attn_kernel(
    const void* __restrict__ idxp, float* __restrict__ out) {
    int n = blockIdx.x;
    int tid = threadIdx.x;
    __shared__ float s_att[KCTX];
    __shared__ int   s_idx[KCTX];

    if (tid < KCTX) {
        long long id;
        if (g_is64) id = ((const long long*)idxp)[(long long)n * KCTX + tid];
        else        id = ((const int*)idxp)[n * KCTX + tid];
        int  ii    = (int)id;
        bool valid = (id >= 0);
        float score;
        if (valid) {
            float sc = g_st[n].x + g_st[ii].y;          // si + a_b + t[idx]
            score = sc > 0.f ? sc : ALPHA * sc;         // LeakyReLU
        } else {
            score = NEG_INF;
        }
        // warp softmax over the 32 context slots
        float m = score;
        for (int o = 16; o > 0; o >>= 1)
            m = fmaxf(m, __shfl_xor_sync(0xffffffffu, m, o));
        float e = valid ? __expf(score - m) : 0.f;
        float s = e;
        for (int o = 16; o > 0; o >>= 1)
            s += __shfl_xor_sync(0xffffffffu, s, o);
        s_att[tid] = (s > 0.f) ? (e / s) : 0.f;
        s_idx[tid] = ii;
    }
    __syncthreads();

    float acc0 = 0.f, acc1 = 0.f, acc2 = 0.f;
#pragma unroll
    for (int k = 0; k < KCTX; k++) {
        float a = s_att[k];
        if (a != 0.f) {                  // uniform across block; skips padding
            const float* row = g_Whall + s_idx[k] * HID;
            acc0 += a * row[tid];
            acc1 += a * row[tid + 128];
            acc2 += a * row[tid + 256];
        }
    }
    int o = n * HID;
    out[o + tid]       = acc0;
    out[o + tid + 128] = acc1;
    out[o + tid + 256] = acc2;
}

// ---------------- launch -----------------------------------------------------
extern "C" void kernel_launch(void* const* d_in, const int* in_sizes, int n_in,
                              void* d_out, int out_size) {
    const float* h_i = (const float*)d_in[0];
    const void*  idx = d_in[1];
    const float* W_i = (const float*)d_in[2];
    const float* W_j = (const float*)d_in[3];
    const float* a_i = (const float*)d_in[4];
    const float* a_j = (const float*)d_in[5];
    const float* a_b = (const float*)d_in[6];
    float* out = (float*)d_out;

    detect_kernel<<<1, 256>>>((const int*)idx);
    vu_kernel<<<IN_F, 128>>>(W_i, W_j, a_i, a_j);

    float* whall_ptr = nullptr;  // kernels reference g_Whall directly
    (void)whall_ptr;
    dim3 gemm_grid(HID / BN, N_BOX / BM);
    {
        // C = g_Whall — pass via device symbol: use a small shim kernel? No:
        // sgemm writes through its C argument; get address at launch via
        // a __device__ global is not host-visible without cudaGetSymbolAddress
        // (which is allowed — it's not an allocation). Done below.
    }
    void* whall_dev = nullptr;
    cudaGetSymbolAddress(&whall_dev, g_Whall);
    sgemm_kernel<<<gemm_grid, 256>>>(h_i, W_j, (float*)whall_dev);

    st_kernel<<<(N_BOX * 32 + 255) / 256, 256>>>(h_i, a_b);
    attn_kernel<<<N_BOX, 128>>>(idx, out);
}